// round 5
// baseline (speedup 1.0000x reference)
#include <cuda_runtime.h>
#include <cstdint>

#define B_DIM  64
#define S_DIM  2048
#define D_DIM  6
#define H_DIM  8
#define NC     32
#define CHUNK  8             // timesteps per chunk
#define NCHUNK 256           // chunks per chain
#define GRP    16            // chunks per scan group
#define NGRP   16            // groups per chain
#define EPS    1e-8f

// ---- scratch (device globals; no allocation allowed) ----
// g_psi: intra-chunk prefixes, component-major  [b][h][j][k][c]   (134 MB)
__device__ float g_psi  [(size_t)B_DIM * H_DIM * CHUNK * NC * NCHUNK];
// g_chunk: normalized chunk products           [b][h][c][k]      (16.8 MB)
__device__ float g_chunk[(size_t)B_DIM * H_DIM * NCHUNK * NC];
// g_carry: per-chunk exclusive carries, SoA    [b][h][k][c]      (16.8 MB)
__device__ float g_carry[(size_t)B_DIM * H_DIM * NC * NCHUNK];

// ---- Cl(4,1) sign machinery (validated R1) ----
__host__ __device__ constexpr int cpopc(int v) {
    int c = 0;
    for (int i = 0; i < 5; ++i) c += (v >> i) & 1;
    return c;
}
__host__ __device__ constexpr bool sign_neg(int a, int b) {
    int s = 0;
    for (int t = 1; t < 5; ++t) s += cpopc((a >> t) & b);
    if (a & b & 16) s += 1;           // metric: e5*e5 = -1
    return (s & 1) != 0;
}

__device__ __forceinline__ void gp(const float* __restrict__ a,
                                   const float* __restrict__ b,
                                   float* __restrict__ o) {
#pragma unroll
    for (int k = 0; k < NC; ++k) {
        float acc = 0.f;
#pragma unroll
        for (int i = 0; i < NC; ++i) {
            if (sign_neg(i, i ^ k)) acc = fmaf(-a[i], b[i ^ k], acc);
            else                    acc = fmaf( a[i], b[i ^ k], acc);
        }
        o[k] = acc;
    }
}

__device__ __forceinline__ float rnorm(const float* v) {   // 1/|v| via MUFU.RSQ
    float ss = 0.f;
#pragma unroll
    for (int k = 0; k < NC; ++k) ss = fmaf(v[k], v[k], ss);
    return rsqrtf(ss + 1e-30f);
}

__device__ __forceinline__ void load32(const float* __restrict__ p, float* v) {
#pragma unroll
    for (int q = 0; q < 8; ++q) {
        float4 t = reinterpret_cast<const float4*>(p)[q];
        v[4 * q + 0] = t.x; v[4 * q + 1] = t.y;
        v[4 * q + 2] = t.z; v[4 * q + 3] = t.w;
    }
}
__device__ __forceinline__ void store32(float* __restrict__ p, const float* v) {
#pragma unroll
    for (int q = 0; q < 8; ++q) {
        float4 t;
        t.x = v[4 * q + 0]; t.y = v[4 * q + 1];
        t.z = v[4 * q + 2]; t.w = v[4 * q + 3];
        reinterpret_cast<float4*>(p)[q] = t;
    }
}

// ---- f32x2 packed helpers ----
__device__ __forceinline__ unsigned long long pack2(float lo, float hi) {
    unsigned long long r;
    asm("mov.b64 %0, {%1, %2};" : "=l"(r) : "f"(lo), "f"(hi));
    return r;
}
__device__ __forceinline__ void unpack2(unsigned long long v, float& lo, float& hi) {
    asm("mov.b64 {%0, %1}, %2;" : "=f"(lo), "=f"(hi) : "l"(v));
}
__device__ __forceinline__ unsigned long long ffma2(unsigned long long a,
                                                    unsigned long long b,
                                                    unsigned long long c) {
    unsigned long long d;
    asm("fma.rn.f32x2 %0, %1, %2, %3;" : "=l"(d) : "l"(a), "l"(b), "l"(c));
    return d;
}

// ---- per-lane sign setup for shuffle GP (validated R1) ----
__device__ __forceinline__ void lane_sign(int k, unsigned& smask, bool& gneg) {
    int m = 0;
#pragma unroll
    for (int p = 0; p < 5; ++p) {
        int bit = __popc(k & ((1 << p) - 1)) & 1;
        m |= bit << p;
    }
    m ^= (k & 16);
    smask = 0u;
#pragma unroll
    for (int i = 0; i < NC; ++i)
        smask |= (unsigned)(__popc(i & m) & 1) << i;
    int pc = __popc(k);
    gneg = (((pc * (pc - 1) / 2) + ((k >> 4) & 1)) & 1) != 0;
}

// one shuffle-GP step with normalization: r <- N(GP(a, r)); a pre-negated by gneg
__device__ __forceinline__ float shfl_gp_norm(float a, float r, unsigned smask) {
    float acc = 0.f;
#pragma unroll
    for (int i = 0; i < NC; ++i) {
        float va = __shfl_sync(0xffffffffu, a, i);
        float vr = __shfl_xor_sync(0xffffffffu, r, i);
        unsigned sb = (smask << (31 - i)) & 0x80000000u;
        va = __uint_as_float(__float_as_uint(va) ^ sb);
        acc = fmaf(va, vr, acc);
    }
    float ss = acc * acc;
#pragma unroll
    for (int o = 16; o > 0; o >>= 1) ss += __shfl_xor_sync(0xffffffffu, ss, o);
    return acc * rsqrtf(ss + 1e-30f);
}

// ---- Kernel AB: fused delta + chunk products + intra-chunk prefixes ----
// thread per (b,h,c); NO intermediate normalization (scale cancels downstream);
// prefixes stored SoA [b][h][j][k][c] -> 32 coalesced STG.32 per step.
__global__ void __launch_bounds__(128) kAB(const float* __restrict__ x,
                                           const float* __restrict__ Win,
                                           const float* __restrict__ bin) {
    __shared__ float sW[D_DIM * H_DIM * NC];   // 6 KB
    __shared__ float sB[H_DIM * NC];
    for (int i = threadIdx.x; i < D_DIM * H_DIM * NC; i += blockDim.x) sW[i] = Win[i];
    for (int i = threadIdx.x; i < H_DIM * NC; i += blockDim.x) sB[i] = bin[i];
    __syncthreads();

    int tid = blockIdx.x * blockDim.x + threadIdx.x;   // 0 .. 131071
    int c = tid & (NCHUNK - 1);                        // lane-consecutive
    int h = (tid >> 8) & (H_DIM - 1);
    int b = tid >> 11;
    const float* bcol = sB + h * NC;

    float P[NC];
#pragma unroll 1
    for (int j = 0; j < CHUNK; ++j) {
        int t = c * CHUNK + j;
        const float* xr = x + ((size_t)b * S_DIM + t) * D_DIM;
        float2 x01 = reinterpret_cast<const float2*>(xr)[0];
        float2 x23 = reinterpret_cast<const float2*>(xr)[1];
        float2 x45 = reinterpret_cast<const float2*>(xr)[2];
        float xv[D_DIM] = {x01.x, x01.y, x23.x, x23.y, x45.x, x45.y};

        float u[NC];
#pragma unroll
        for (int k = 0; k < NC; ++k) {
            float a = bcol[k];
#pragma unroll
            for (int d = 0; d < D_DIM; ++d)
                a = fmaf(xv[d], sW[d * (H_DIM * NC) + h * NC + k], a);
            u[k] = a;
        }
        u[0] += 1.f;                      // delta direction; norm skipped (cancels)

        if (j == 0) {
#pragma unroll
            for (int k = 0; k < NC; ++k) P[k] = u[k];
        } else {
            float O[NC];
            gp(u, P, O);                  // newer delta on the LEFT
#pragma unroll
            for (int k = 0; k < NC; ++k) P[k] = O[k];
        }
        // SoA store: [b][h][j][k][c]
        size_t base = ((size_t)((b * H_DIM + h) * CHUNK + j)) * NC * NCHUNK + c;
#pragma unroll
        for (int k = 0; k < NC; ++k) g_psi[base + (size_t)k * NCHUNK] = P[k];
    }
    // normalize chunk total once (conditioning for the scan), store [b][h][c][k]
    float inv = rnorm(P);
    float Pn[NC];
#pragma unroll
    for (int k = 0; k < NC; ++k) Pn[k] = P[k] * inv;
    store32(g_chunk + ((size_t)(b * H_DIM + h) * NCHUNK + c) * NC, Pn);
}

// ---- Kernel C: full per-chain scan in ONE block (fuses old kC1/kC2/kC3) ----
// block = 512 threads = 16 warps, one block per chain (b,h). Scan held in smem.
__global__ void __launch_bounds__(512) kC() {
    __shared__ float s_scan[NCHUNK * 33];   // padded rows: bank-conflict-free
    __shared__ float s_tot[NGRP * NC];      // group exclusive carries

    int chain = blockIdx.x;                 // b*8 + h
    int tid = threadIdx.x;
    int wid = tid >> 5;
    int k = tid & 31;
    unsigned smask; bool gneg;
    lane_sign(k, smask, gneg);
    size_t cb = (size_t)chain * NCHUNK * NC;

    // phase 1: warp g scans its 16-chunk group (inclusive), results to smem
    {
        int g = wid;
        float r = g_chunk[cb + (size_t)(g * GRP) * NC + k];
        s_scan[(g * GRP) * 33 + k] = r;
#pragma unroll
        for (int j = 1; j < GRP; ++j) {
            float a = g_chunk[cb + (size_t)(g * GRP + j) * NC + k];
            if (gneg) a = -a;
            r = shfl_gp_norm(a, r, smask);
            s_scan[(g * GRP + j) * 33 + k] = r;
        }
    }
    __syncthreads();

    // phase 2: warp 0 does exclusive scan of the 16 group totals
    if (wid == 0) {
        float r = (k == 0) ? 1.f : 0.f;     // identity rotor
#pragma unroll
        for (int g = 0; g < NGRP; ++g) {
            s_tot[g * NC + k] = r;
            float a = s_scan[(g * GRP + GRP - 1) * 33 + k];
            if (gneg) a = -a;
            r = shfl_gp_norm(a, r, smask);
        }
    }
    __syncthreads();

    // phase 3: threads 0..255 compute per-chunk exclusive carries (no norm needed)
    if (tid < NCHUNK) {
        int c = tid, g = c >> 4;
        float G[NC], O[NC];
#pragma unroll
        for (int q = 0; q < NC; ++q) G[q] = s_tot[g * NC + q];
        if ((c & (GRP - 1)) == 0) {
#pragma unroll
            for (int q = 0; q < NC; ++q) O[q] = G[q];
        } else {
            float A[NC];
#pragma unroll
            for (int q = 0; q < NC; ++q) A[q] = s_scan[(c - 1) * 33 + q];
            gp(A, G, O);                    // within-group inclusive (newer) on LEFT
        }
        // SoA store: [b][h][k][c]
        size_t ob = (size_t)chain * NC * NCHUNK + c;
#pragma unroll
        for (int q = 0; q < NC; ++q) g_carry[ob + (size_t)q * NCHUNK] = O[q];
    }
}

// ---- kDE: fused expand + projection. warp = (b, c_hi, j); lane = c_low ----
__global__ void __launch_bounds__(128) kDE(const float* __restrict__ Wout,
                                           const float* __restrict__ bout,
                                           float* __restrict__ out) {
    __shared__ __align__(16) float sW[H_DIM * NC * NC];   // 32 KB
    __shared__ float sb[NC];
    for (int i = threadIdx.x; i < H_DIM * NC * NC; i += blockDim.x) sW[i] = Wout[i];
    if (threadIdx.x < NC) sb[threadIdx.x] = bout[threadIdx.x];
    __syncthreads();

    int tid = blockIdx.x * blockDim.x + threadIdx.x;
    int lane = tid & 31;
    int w = tid >> 5;
    int j  = w & (CHUNK - 1);        // step within chunk
    int ch = (w >> 3) & 7;           // chunk-high
    int b  = w >> 6;
    int c  = ch * 32 + lane;         // chunk index, lane-consecutive

    unsigned long long acc2[16];
#pragma unroll
    for (int q = 0; q < 16; ++q) acc2[q] = pack2(sb[2 * q], sb[2 * q + 1]);

#pragma unroll 1
    for (int h = 0; h < H_DIM; ++h) {
        float A[NC], Cv[NC], O[NC];
        size_t pb = ((size_t)((b * H_DIM + h) * CHUNK + j)) * NC * NCHUNK + c;
#pragma unroll
        for (int k = 0; k < NC; ++k) A[k] = g_psi[pb + (size_t)k * NCHUNK];
        size_t cbb = (size_t)(b * H_DIM + h) * NC * NCHUNK + c;
#pragma unroll
        for (int k = 0; k < NC; ++k) Cv[k] = g_carry[cbb + (size_t)k * NCHUNK];

        gp(A, Cv, O);                 // prefix (newer) on LEFT
        float inv = rnorm(O);         // psi must be unit before bias add

#pragma unroll
        for (int m = 0; m < NC; ++m) {
            float pm = O[m] * inv;
            unsigned long long pm2 = pack2(pm, pm);
            const ulonglong2* wr =
                reinterpret_cast<const ulonglong2*>(sW + (size_t)(h * NC + m) * NC);
#pragma unroll
            for (int q = 0; q < 8; ++q) {
                ulonglong2 wv = wr[q];    // warp-uniform smem address -> broadcast
                acc2[2 * q + 0] = ffma2(pm2, wv.x, acc2[2 * q + 0]);
                acc2[2 * q + 1] = ffma2(pm2, wv.y, acc2[2 * q + 1]);
            }
        }
    }

    float res[NC];
    float ss = 0.f;
#pragma unroll
    for (int q = 0; q < 16; ++q) {
        float lo, hi;
        unpack2(acc2[q], lo, hi);
        res[2 * q] = lo; res[2 * q + 1] = hi;
        ss = fmaf(lo, lo, fmaf(hi, hi, ss));
    }
    float inv = rsqrtf(ss + 1e-30f);
    size_t row = (size_t)b * S_DIM + (size_t)c * CHUNK + j;
    float4* orow = reinterpret_cast<float4*>(out + row * NC);
#pragma unroll
    for (int q = 0; q < 8; ++q) {
        float4 v;
        v.x = res[4 * q + 0] * inv; v.y = res[4 * q + 1] * inv;
        v.z = res[4 * q + 2] * inv; v.w = res[4 * q + 3] * inv;
        orow[q] = v;
    }
}

extern "C" void kernel_launch(void* const* d_in, const int* in_sizes, int n_in,
                              void* d_out, int out_size) {
    const float* x    = (const float*)d_in[0];
    const float* Win  = (const float*)d_in[1];
    const float* bin  = (const float*)d_in[2];
    const float* Wout = (const float*)d_in[3];
    const float* bout = (const float*)d_in[4];
    float* out = (float*)d_out;

    kAB<<<(B_DIM * H_DIM * NCHUNK) / 128, 128>>>(x, Win, bin);
    kC<<<B_DIM * H_DIM, 512>>>();
    kDE<<<(B_DIM * S_DIM) / 128, 128>>>(Wout, bout, out);
}